// round 5
// baseline (speedup 1.0000x reference)
#include <cuda_runtime.h>
#include <cstdint>

#define BB   8
#define SS   128
#define DD   300
#define EE   50
#define DEPC 50
#define RROWS 8
#define NTHR 512

// ---------------- scratch (static device globals; no allocation) ----------------
__device__ float g_M [BB * SS * SS];     // mean-over-experts adjacency
__device__ float g_Pa[BB * SS * DEPC];   // node @ Wa^T
__device__ float g_Pb[BB * SS * DEPC];   // node @ Wb^T

using ull = unsigned long long;

// ---------------- f32x2 packed-math helpers ----------------
__device__ __forceinline__ ull pk2(float x, float y) {
    ull r; asm("mov.b64 %0, {%1,%2};" : "=l"(r) : "f"(x), "f"(y)); return r;
}
__device__ __forceinline__ ull f2fma(ull a, ull b, ull c) {
    ull d; asm("fma.rn.f32x2 %0, %1, %2, %3;" : "=l"(d) : "l"(a), "l"(b), "l"(c)); return d;
}
__device__ __forceinline__ ull f2add(ull a, ull b) {
    ull d; asm("add.rn.f32x2 %0, %1, %2;" : "=l"(d) : "l"(a), "l"(b)); return d;
}
__device__ __forceinline__ void upk2(ull v, float& x, float& y) {
    asm("mov.b64 {%0,%1}, %2;" : "=f"(x), "=f"(y) : "l"(v));
}

// =======================================================================
// k_reduce: M[b,s,t] = (1/E)(sum_e wps[b,s,t,e] + sum_e sl[b,e,s,t])
// 1024 blocks, one per (b,s). wps rows staged via COALESCED float4 into smem
// (fixes the stride-200B L1-wavefront explosion); sl loads already coalesced.
// =======================================================================
__global__ __launch_bounds__(256) void k_reduce(const float* __restrict__ wps,
                                                const float* __restrict__ sl) {
    __shared__ float W[128 * EE];     // 25600 B raw wps rows
    __shared__ float Srow[128];
    __shared__ float SL[256];
    const int tid = threadIdx.x;
    const int blk = blockIdx.x;            // = b*128 + s
    const int r0  = blk * 128;             // global (b,s,t) row base
    const int b   = blk >> 7;
    const int s   = blk & 127;

    // Stage A: coalesced float4 load of this block's 128 wps rows (aligned: 25600B/blk)
    const float4* src = reinterpret_cast<const float4*>(wps) + (size_t)blk * 1600;
    float4* W4 = reinterpret_cast<float4*>(W);
    for (int i = tid; i < 1600; i += 256) W4[i] = src[i];

    // sl partial (coalesced: consecutive tid -> consecutive t)
    {
        const int tcol = tid & 127, eh = tid >> 7;     // e-half
        const float* sp = sl + (size_t)b * EE * SS * SS
                             + (size_t)(eh * 25) * SS * SS + s * SS + tcol;
        float acc = 0.f;
#pragma unroll
        for (int e = 0; e < 25; e++) acc += sp[(size_t)e * SS * SS];
        SL[tid] = acc;
    }
    __syncthreads();

    // Stage B: pair of threads sums one smem row (2-way bank conflict max)
    {
        const int row = tid >> 1, eh = tid & 1;
        const float* wr = W + row * EE + eh * 25;
        float s1 = 0.f;
#pragma unroll
        for (int i = 0; i < 25; i++) s1 += wr[i];
        s1 += __shfl_xor_sync(0xffffffffu, s1, 1);
        if (eh == 0) Srow[row] = s1;
    }
    __syncthreads();

    if (tid < 128)
        g_M[r0 + tid] = (Srow[tid] + SL[tid] + SL[tid + 128]) * (1.0f / EE);
}

// =======================================================================
// k_compute: per (b, 8-row group): Ax = M@X ; g = Ax@W^T + b ; LN(ddof=1);
// node = relu ; pa/pb = node @ {Wa,Wb}^T.   512 threads.
// =======================================================================
#define OFF_MSP   0        // 1024  packed M row-pairs [t*4+rp] -> f2 (rows 2rp,2rp+1)
#define OFF_AX    1024     // 3000  Ax f2 [d*5+rp]
#define OFF_NS    4024     // 3000  node f2 [d*5+rp]
#define OFF_H     7024     // 4800  scratch: GH (phase2) / Pp (phase4)
#define OFF_RED   11824    // 128   (16 warps x 8)
#define OFF_MEAN  11952    // 8
#define OFF_INVD  11960    // 8
#define SMEM_FLOATS 11968
#define SMEM_BYTES  (SMEM_FLOATS * 4)

#define MSU(t, rp) (*reinterpret_cast<const ull*>(&MsP[(t) * 4 + (rp)]))
#define AXU(d, rp) (*reinterpret_cast<const ull*>(&AxP[(d) * 5 + (rp)]))
#define NSU(d, rp) (*reinterpret_cast<const ull*>(&NsP[(d) * 5 + (rp)]))

__global__ __launch_bounds__(NTHR, 1) void k_compute(
    const float* __restrict__ x,   const float* __restrict__ Ww,
    const float* __restrict__ Wb,  const float* __restrict__ lna,
    const float* __restrict__ lnb, const float* __restrict__ W1w,
    float* __restrict__ node_out)
{
    extern __shared__ float sm[];
    float*  MsPf  = sm + OFF_MSP;
    float2* MsP   = reinterpret_cast<float2*>(MsPf);
    float2* AxP   = reinterpret_cast<float2*>(sm + OFF_AX);
    float2* NsP   = reinterpret_cast<float2*>(sm + OFF_NS);
    float*  Hf    = sm + OFF_H;
    float*  red   = sm + OFF_RED;
    float*  means = sm + OFF_MEAN;
    float*  invd  = sm + OFF_INVD;

    const int tid = threadIdx.x;
    const int b   = blockIdx.x >> 4;
    const int s0  = (blockIdx.x & 15) * RROWS;

    // ---- load + pack this block's 8 M rows (contiguous 4KB, coalesced) ----
    const float* Mb = g_M + (size_t)(b * SS + s0) * SS;
    for (int i = tid; i < RROWS * SS; i += NTHR) {
        int r = i >> 7, t = i & 127;
        MsPf[(t * 4 + (r >> 1)) * 2 + (r & 1)] = Mb[i];
    }
    __syncthreads();

    // ================= Phase 1: Ax[r][d] = sum_t M[r][t] * X[t][d] ==========
    if (tid < DD) {
        const float* xb = x + (size_t)b * SS * DD + tid;
        ull acc[4] = {0, 0, 0, 0};
#pragma unroll 4
        for (int t = 0; t < SS; t++) {
            float xv = xb[(size_t)t * DD];
            ull x2 = pk2(xv, xv);
#pragma unroll
            for (int rp = 0; rp < 4; rp++) acc[rp] = f2fma(MSU(t, rp), x2, acc[rp]);
        }
#pragma unroll
        for (int rp = 0; rp < 4; rp++)
            *reinterpret_cast<ull*>(&AxP[tid * 5 + rp]) = acc[rp];
    }
    __syncthreads();

    // ================= Phase 2: g = Ax @ W^T + b  (150 j-pairs x 3 d-thirds) =
    ull a0[4] = {0, 0, 0, 0}, a1[4] = {0, 0, 0, 0};
    const int jp = tid / 3, dh = tid - 3 * jp;     // jp<150 for tid<450
    const int j0 = jp * 2, j1 = j0 + 1;
    const bool p2act = (tid < 450);
    if (p2act) {
        const float2* w0 = reinterpret_cast<const float2*>(Ww + (size_t)j0 * DD + dh * 100);
        const float2* w1 = reinterpret_cast<const float2*>(Ww + (size_t)j1 * DD + dh * 100);
        const int dbase = dh * 100;
#pragma unroll 5
        for (int i = 0; i < 50; i++) {
            float2 wa = w0[i], wb2 = w1[i];
            int d = dbase + 2 * i;
            ull wax = pk2(wa.x, wa.x), wbx = pk2(wb2.x, wb2.x);
#pragma unroll
            for (int rp = 0; rp < 4; rp++) {
                ull ax = AXU(d, rp);
                a0[rp] = f2fma(wax, ax, a0[rp]);
                a1[rp] = f2fma(wbx, ax, a1[rp]);
            }
            ull way = pk2(wa.y, wa.y), wby = pk2(wb2.y, wb2.y);
#pragma unroll
            for (int rp = 0; rp < 4; rp++) {
                ull ax = AXU(d + 1, rp);
                a0[rp] = f2fma(way, ax, a0[rp]);
                a1[rp] = f2fma(wby, ax, a1[rp]);
            }
        }
    }
    if (p2act && dh) {                       // thirds 1,2 publish
        ull* GH = reinterpret_cast<ull*>(Hf);
        int base = (jp * 2 + (dh - 1)) * 8;
#pragma unroll
        for (int rp = 0; rp < 4; rp++) { GH[base + rp] = a0[rp]; GH[base + 4 + rp] = a1[rp]; }
    }
    __syncthreads();

    float gj0[RROWS], gj1[RROWS];
    const bool owner = p2act && (dh == 0);
    if (owner) {
        ull* GH = reinterpret_cast<ull*>(Hf);
        float bj0 = Wb[j0], bj1 = Wb[j1];
#pragma unroll
        for (int rp = 0; rp < 4; rp++) {
            ull f0 = f2add(f2add(a0[rp], GH[(jp * 2) * 8 + rp]),     GH[(jp * 2 + 1) * 8 + rp]);
            ull f1 = f2add(f2add(a1[rp], GH[(jp * 2) * 8 + 4 + rp]), GH[(jp * 2 + 1) * 8 + 4 + rp]);
            upk2(f0, gj0[2 * rp], gj0[2 * rp + 1]);
            upk2(f1, gj1[2 * rp], gj1[2 * rp + 1]);
        }
#pragma unroll
        for (int r = 0; r < RROWS; r++) { gj0[r] += bj0; gj1[r] += bj1; }
    }

    // ================= Phase 3: LayerNorm (ddof=1) + relu ====================
    const int lane = tid & 31, warp = tid >> 5;
    {
        float s[RROWS];
#pragma unroll
        for (int r = 0; r < RROWS; r++) s[r] = owner ? (gj0[r] + gj1[r]) : 0.f;
#pragma unroll
        for (int off = 16; off; off >>= 1)
#pragma unroll
            for (int r = 0; r < RROWS; r++) s[r] += __shfl_down_sync(0xffffffffu, s[r], off);
        if (lane == 0)
#pragma unroll
            for (int r = 0; r < RROWS; r++) red[warp * RROWS + r] = s[r];
    }
    __syncthreads();
    if (tid < RROWS) {
        float s = 0.f;
#pragma unroll
        for (int w = 0; w < NTHR / 32; w++) s += red[w * RROWS + tid];
        means[tid] = s * (1.0f / DD);
    }
    __syncthreads();
    {
        float s[RROWS];
#pragma unroll
        for (int r = 0; r < RROWS; r++) {
            float d0 = owner ? (gj0[r] - means[r]) : 0.f;
            float d1 = owner ? (gj1[r] - means[r]) : 0.f;
            s[r] = d0 * d0 + d1 * d1;
        }
#pragma unroll
        for (int off = 16; off; off >>= 1)
#pragma unroll
            for (int r = 0; r < RROWS; r++) s[r] += __shfl_down_sync(0xffffffffu, s[r], off);
        if (lane == 0)
#pragma unroll
            for (int r = 0; r < RROWS; r++) red[warp * RROWS + r] = s[r];
    }
    __syncthreads();
    if (tid < RROWS) {
        float s = 0.f;
#pragma unroll
        for (int w = 0; w < NTHR / 32; w++) s += red[w * RROWS + tid];
        float stdv = sqrtf(s * (1.0f / (DD - 1)));     // ddof = 1
        invd[tid] = 1.0f / (stdv + 1e-6f);
    }
    __syncthreads();

    if (owner) {
        float la0 = lna[j0], la1 = lna[j1], lb0 = lnb[j0], lb1 = lnb[j1];
        float n0[RROWS], n1[RROWS];
#pragma unroll
        for (int r = 0; r < RROWS; r++) {
            float v0 = la0 * (gj0[r] - means[r]) * invd[r] + lb0;
            float v1 = la1 * (gj1[r] - means[r]) * invd[r] + lb1;
            n0[r] = v0 > 0.f ? v0 : 0.f;
            n1[r] = v1 > 0.f ? v1 : 0.f;
            *reinterpret_cast<float2*>(node_out + (size_t)(b * SS + s0 + r) * DD + j0) =
                make_float2(n0[r], n1[r]);
        }
#pragma unroll
        for (int rp = 0; rp < 4; rp++) {
            NsP[j0 * 5 + rp] = make_float2(n0[2 * rp], n0[2 * rp + 1]);
            NsP[j1 * 5 + rp] = make_float2(n1[2 * rp], n1[2 * rp + 1]);
        }
    }
    __syncthreads();

    // ================= Phase 4: pa/pb, 3-way d-split over 300 threads ========
    float2* Pp = reinterpret_cast<float2*>(Hf);     // 1200 f2 (GH dead)
    if (tid < 300) {
        int o = tid / 3, seg = tid - 3 * o;         // o in [0,100): e=o%50, half=o/50
        int e = o % DEPC, half = o / DEPC;
        const float2* w2 = reinterpret_cast<const float2*>(
            W1w + (size_t)e * (2 * DD) + half * DD + seg * 100);
        ull acc[4] = {0, 0, 0, 0};
        int dbase = seg * 100;
#pragma unroll 5
        for (int i = 0; i < 50; i++) {
            float2 wv = w2[i];
            int d = dbase + 2 * i;
            ull wx = pk2(wv.x, wv.x);
#pragma unroll
            for (int rp = 0; rp < 4; rp++) acc[rp] = f2fma(wx, NSU(d, rp), acc[rp]);
            ull wy = pk2(wv.y, wv.y);
#pragma unroll
            for (int rp = 0; rp < 4; rp++) acc[rp] = f2fma(wy, NSU(d + 1, rp), acc[rp]);
        }
#pragma unroll
        for (int rp = 0; rp < 4; rp++)
            Pp[(o * 3 + seg) * 4 + rp] = *reinterpret_cast<float2*>(&acc[rp]);
    }
    __syncthreads();

    if (tid < 400) {
        int o = tid >> 2, rp = tid & 3;
        int e = o % DEPC, half = o / DEPC;
        float sx = 0.f, sy = 0.f;
#pragma unroll
        for (int s = 0; s < 3; s++) {
            float2 p = Pp[(o * 3 + s) * 4 + rp];
            sx += p.x; sy += p.y;
        }
        float* dst = (half == 0 ? g_Pa : g_Pb) + (size_t)(b * SS + s0) * DEPC + e;
        dst[(2 * rp)     * DEPC] = sx;
        dst[(2 * rp + 1) * DEPC] = sy;
    }
}

// =======================================================================
// k_edge: edge[b,i,j,e] = pa[b,j,e] + pb[b,i,e] + W1_b[e]
// 512 blocks x 2 rows: pa values loaded ONCE into regs, reused across rows.
// 400 threads = 16 j-slots x 25 e-pairs; body = pure STG.64 stream.
// =======================================================================
__global__ __launch_bounds__(400) void k_edge(const float* __restrict__ W1b,
                                              float* __restrict__ edge) {
    const int bi0 = blockIdx.x * 2;      // first of 2 (b,i) rows
    const int b   = bi0 >> 7;
    const int tid = threadIdx.x;
    const int e2  = tid % 25;
    const int j0  = tid / 25;

    float2 w = reinterpret_cast<const float2*>(W1b)[e2];
    const ull* pa = reinterpret_cast<const ull*>(g_Pa + (size_t)b * SS * DEPC);
    ull pav[8];
#pragma unroll
    for (int k = 0; k < 8; k++) pav[k] = pa[(j0 + 16 * k) * 25 + e2];

#pragma unroll
    for (int r = 0; r < 2; r++) {
        int bi = bi0 + r;
        float2 pv = reinterpret_cast<const float2*>(g_Pb + (size_t)bi * DEPC)[e2];
        ull pr = pk2(pv.x + w.x, pv.y + w.y);
        ull* out = reinterpret_cast<ull*>(edge + (size_t)bi * SS * DEPC);
#pragma unroll
        for (int k = 0; k < 8; k++) out[(j0 + 16 * k) * 25 + e2] = f2add(pav[k], pr);
    }
}

// =======================================================================
extern "C" void kernel_launch(void* const* d_in, const int* in_sizes, int n_in,
                              void* d_out, int out_size) {
    const float* wps = (const float*)d_in[0];
    /* d_in[1] = weight_adj (int64) — unused */
    const float* x   = (const float*)d_in[2];
    const float* sl  = (const float*)d_in[3];
    const float* Ww  = (const float*)d_in[4];
    const float* Wb  = (const float*)d_in[5];
    const float* lna = (const float*)d_in[6];
    const float* lnb = (const float*)d_in[7];
    const float* W1w = (const float*)d_in[8];
    const float* W1b = (const float*)d_in[9];

    float* out  = (float*)d_out;
    float* node = out;                       // B*S*D floats
    float* edge = out + BB * SS * DD;        // B*S*S*DEP floats

    cudaFuncSetAttribute((const void*)k_compute,
                         cudaFuncAttributeMaxDynamicSharedMemorySize, SMEM_BYTES);

    k_reduce <<<BB * SS, 256>>>(wps, sl);
    k_compute<<<BB * (SS / RROWS), NTHR, SMEM_BYTES>>>(x, Ww, Wb, lna, lnb, W1w, node);
    k_edge   <<<BB * SS / 2, 400>>>(W1b, edge);
}

// round 7
// speedup vs baseline: 1.2589x; 1.2589x over previous
#include <cuda_runtime.h>
#include <cstdint>

#define BB   8
#define SS   128
#define DD   300
#define EE   50
#define DEPC 50
#define RROWS 8
#define NTHR 512

__device__ float g_M [BB * SS * SS];
__device__ float g_Pa[BB * SS * DEPC];
__device__ float g_Pb[BB * SS * DEPC];

using ull = unsigned long long;

__device__ __forceinline__ ull pk2(float x, float y) {
    ull r; asm("mov.b64 %0, {%1,%2};" : "=l"(r) : "f"(x), "f"(y)); return r;
}
__device__ __forceinline__ ull f2fma(ull a, ull b, ull c) {
    ull d; asm("fma.rn.f32x2 %0, %1, %2, %3;" : "=l"(d) : "l"(a), "l"(b), "l"(c)); return d;
}
__device__ __forceinline__ ull f2add(ull a, ull b) {
    ull d; asm("add.rn.f32x2 %0, %1, %2;" : "=l"(d) : "l"(a), "l"(b)); return d;
}
__device__ __forceinline__ void upk2(ull v, float& x, float& y) {
    asm("mov.b64 {%0,%1}, %2;" : "=f"(x), "=f"(y) : "l"(v));
}

// =======================================================================
// k_reduce: M[b,s,t] = (1/E)(sum_e wps[b,s,t,e] + sum_e sl[b,e,s,t])
// Stage-A explicit 6-load batch + tail -> MLP ~7 (fractional trip count
// previously blocked unrolling, serializing LDG->STS round trips).
// =======================================================================
__global__ __launch_bounds__(256) void k_reduce(const float* __restrict__ wps,
                                                const float* __restrict__ sl) {
    __shared__ float W[128 * EE];
    __shared__ float Srow[128];
    __shared__ float SL[256];
    const int tid = threadIdx.x;
    const int blk = blockIdx.x;            // b*128 + s
    const int b   = blk >> 7;
    const int s   = blk & 127;

    const float4* src = reinterpret_cast<const float4*>(wps) + (size_t)blk * 1600;
    float4* W4 = reinterpret_cast<float4*>(W);
    float4 v[6];
#pragma unroll
    for (int k = 0; k < 6; k++) v[k] = src[tid + 256 * k];
    float4 v6;
    const bool tail = tid < 64;
    if (tail) v6 = src[tid + 1536];

    // sl partial (independent loads, MLP 25)
    float slacc = 0.f;
    {
        const int tcol = tid & 127, eh = tid >> 7;
        const float* sp = sl + (size_t)b * EE * SS * SS
                             + (size_t)(eh * 25) * SS * SS + s * SS + tcol;
#pragma unroll
        for (int e = 0; e < 25; e++) slacc += sp[(size_t)e * SS * SS];
    }

#pragma unroll
    for (int k = 0; k < 6; k++) W4[tid + 256 * k] = v[k];
    if (tail) W4[tid + 1536] = v6;
    SL[tid] = slacc;
    __syncthreads();

    {
        const int row = tid >> 1, eh = tid & 1;
        const float* wr = W + row * EE + eh * 25;
        float s1 = 0.f;
#pragma unroll
        for (int i = 0; i < 25; i++) s1 += wr[i];
        s1 += __shfl_xor_sync(0xffffffffu, s1, 1);
        if (eh == 0) Srow[row] = s1;
    }
    __syncthreads();

    if (tid < 128)
        g_M[blk * 128 + tid] = (Srow[tid] + SL[tid] + SL[tid + 128]) * (1.0f / EE);
}

// =======================================================================
// k_compute — weights STAGED COALESCED into smem (kills the 1200B-stride
// LDG wavefront explosion that dominated all previous rounds).
// =======================================================================
#define OFF_MSP   0        // 1024 f : packed M row-pairs [t*4+rp] f2
#define OFF_AX    1024     // 2400 f : Ax f2 [d*4+rp]
#define OFF_NS    3424     // 2400 f : g then node, f2 [j*4+rp]
#define OFF_WS    5824     // 30200 f: staged weight chunk (f2 stride 151)
#define OFF_GH    36024    // 3200 f : publish scratch (400*4 ull)
#define OFF_RED   39224    // 128
#define OFF_MEAN  39352    // 8
#define OFF_INVD  39360    // 8
#define SMEM_FLOATS 39368
#define SMEM_BYTES  (SMEM_FLOATS * 4)

__global__ __launch_bounds__(NTHR, 1) void k_compute(
    const float* __restrict__ x,   const float* __restrict__ Ww,
    const float* __restrict__ Wb,  const float* __restrict__ lna,
    const float* __restrict__ lnb, const float* __restrict__ W1w,
    float* __restrict__ node_out)
{
    extern __shared__ float sm[];
    float*  MsPf  = sm + OFF_MSP;
    float2* MsP   = reinterpret_cast<float2*>(MsPf);
    float2* AxP   = reinterpret_cast<float2*>(sm + OFF_AX);
    float2* NsP   = reinterpret_cast<float2*>(sm + OFF_NS);
    float2* Ws2   = reinterpret_cast<float2*>(sm + OFF_WS);
    ull*    GH    = reinterpret_cast<ull*>(sm + OFF_GH);
    float*  red   = sm + OFF_RED;
    float*  means = sm + OFF_MEAN;
    float*  invd  = sm + OFF_INVD;

    const int tid = threadIdx.x;
    const int b   = blockIdx.x >> 4;
    const int s0  = (blockIdx.x & 15) * RROWS;
    const int seg = tid / 100;           // 0..4 active (tid<500)
    const int oj  = tid - seg * 100;

    // ---- pack this block's 8 M rows ----
    const float* Mb = g_M + (size_t)(b * SS + s0) * SS;
    for (int i = tid; i < RROWS * SS; i += NTHR) {
        int r = i >> 7, t = i & 127;
        MsPf[(t * 4 + (r >> 1)) * 2 + (r & 1)] = Mb[i];
    }
    __syncthreads();

    // ================= Phase 1: Ax[r][d] = sum_t M[r][t]*X[t][d] ============
    if (tid < DD) {
        const float* xb = x + (size_t)b * SS * DD + tid;
        const ulonglong2* mv = reinterpret_cast<const ulonglong2*>(MsP);
        ull acc[4] = {0, 0, 0, 0};
        for (int t0 = 0; t0 < SS; t0 += 16) {
            float xv[16];
#pragma unroll
            for (int u = 0; u < 16; u++) xv[u] = xb[(size_t)(t0 + u) * DD];
#pragma unroll
            for (int u = 0; u < 16; u++) {
                ull x2 = pk2(xv[u], xv[u]);
                ulonglong2 m0 = mv[(t0 + u) * 2], m1 = mv[(t0 + u) * 2 + 1];
                acc[0] = f2fma(m0.x, x2, acc[0]);
                acc[1] = f2fma(m0.y, x2, acc[1]);
                acc[2] = f2fma(m1.x, x2, acc[2]);
                acc[3] = f2fma(m1.y, x2, acc[3]);
            }
        }
#pragma unroll
        for (int rp = 0; rp < 4; rp++)
            *reinterpret_cast<ull*>(&AxP[tid * 4 + rp]) = acc[rp];
    }
    __syncthreads();

    // ================= Phase 2: g = Ax @ W^T + b, 3 staged chunks ===========
    for (int c = 0; c < 3; c++) {
        if (tid < 500) {
            const float2* srcw = reinterpret_cast<const float2*>(Ww) + (size_t)c * 15000;
            float2 sv[30];
#pragma unroll
            for (int k = 0; k < 30; k++) sv[k] = srcw[k * 500 + tid];
#pragma unroll
            for (int k = 0; k < 30; k++) {
                int idx = k * 500 + tid;
                int row = idx / 150, col = idx - row * 150;
                Ws2[row * 151 + col] = sv[k];
            }
        }
        __syncthreads();

        ull acc[4] = {0, 0, 0, 0};
        if (tid < 500) {
            const float2* wr = Ws2 + oj * 151 + seg * 30;
            const int dbase = seg * 60;
            const ulonglong2* axv = reinterpret_cast<const ulonglong2*>(AxP);
#pragma unroll 6
            for (int i = 0; i < 30; i++) {
                float2 wv = wr[i];
                int d = dbase + 2 * i;
                ulonglong2 p0 = axv[d * 2],     p1 = axv[d * 2 + 1];
                ulonglong2 q0 = axv[d * 2 + 2], q1 = axv[d * 2 + 3];
                ull wx = pk2(wv.x, wv.x);
                acc[0] = f2fma(wx, p0.x, acc[0]);
                acc[1] = f2fma(wx, p0.y, acc[1]);
                acc[2] = f2fma(wx, p1.x, acc[2]);
                acc[3] = f2fma(wx, p1.y, acc[3]);
                ull wy = pk2(wv.y, wv.y);
                acc[0] = f2fma(wy, q0.x, acc[0]);
                acc[1] = f2fma(wy, q0.y, acc[1]);
                acc[2] = f2fma(wy, q1.x, acc[2]);
                acc[3] = f2fma(wy, q1.y, acc[3]);
            }
        }
        if (tid < 500 && seg) {
            int base = ((seg - 1) * 100 + oj) * 4;
#pragma unroll
            for (int rp = 0; rp < 4; rp++) GH[base + rp] = acc[rp];
        }
        __syncthreads();
        if (tid < 100) {
            int j = c * 100 + tid;
            float bj = Wb[j];
            ull b2 = pk2(bj, bj);
#pragma unroll
            for (int rp = 0; rp < 4; rp++) {
                ull v = acc[rp];
#pragma unroll
                for (int s = 0; s < 4; s++) v = f2add(v, GH[(s * 100 + tid) * 4 + rp]);
                *reinterpret_cast<ull*>(&NsP[j * 4 + rp]) = f2add(v, b2);
            }
        }
        __syncthreads();
    }

    // ================= Phase 3: LayerNorm (ddof=1) + relu ===================
    const int lane = tid & 31, warp = tid >> 5;
    float gj[RROWS];
    const bool jown = (tid < DD);
    if (jown) {
        const ulonglong2* nv = reinterpret_cast<const ulonglong2*>(NsP + tid * 4);
        ulonglong2 a = nv[0], bq = nv[1];
        upk2(a.x,  gj[0], gj[1]); upk2(a.y,  gj[2], gj[3]);
        upk2(bq.x, gj[4], gj[5]); upk2(bq.y, gj[6], gj[7]);
    }
    {
        float s[RROWS];
#pragma unroll
        for (int r = 0; r < RROWS; r++) s[r] = jown ? gj[r] : 0.f;
#pragma unroll
        for (int off = 16; off; off >>= 1)
#pragma unroll
            for (int r = 0; r < RROWS; r++) s[r] += __shfl_down_sync(0xffffffffu, s[r], off);
        if (lane == 0)
#pragma unroll
            for (int r = 0; r < RROWS; r++) red[warp * RROWS + r] = s[r];
    }
    __syncthreads();
    if (tid < RROWS) {
        float s = 0.f;
#pragma unroll
        for (int w = 0; w < NTHR / 32; w++) s += red[w * RROWS + tid];
        means[tid] = s * (1.0f / DD);
    }
    __syncthreads();
    {
        float s[RROWS];
#pragma unroll
        for (int r = 0; r < RROWS; r++) {
            float dv = jown ? (gj[r] - means[r]) : 0.f;
            s[r] = dv * dv;
        }
#pragma unroll
        for (int off = 16; off; off >>= 1)
#pragma unroll
            for (int r = 0; r < RROWS; r++) s[r] += __shfl_down_sync(0xffffffffu, s[r], off);
        if (lane == 0)
#pragma unroll
            for (int r = 0; r < RROWS; r++) red[warp * RROWS + r] = s[r];
    }
    __syncthreads();
    if (tid < RROWS) {
        float s = 0.f;
#pragma unroll
        for (int w = 0; w < NTHR / 32; w++) s += red[w * RROWS + tid];
        float stdv = sqrtf(s * (1.0f / (DD - 1)));   // ddof = 1
        invd[tid] = 1.0f / (stdv + 1e-6f);
    }
    __syncthreads();

    if (jown) {
        float a = lna[tid], bb2 = lnb[tid];
        float nv[RROWS];
#pragma unroll
        for (int r = 0; r < RROWS; r++) {
            float v = a * (gj[r] - means[r]) * invd[r] + bb2;
            nv[r] = v > 0.f ? v : 0.f;
            node_out[(size_t)(b * SS + s0 + r) * DD + tid] = nv[r];
        }
#pragma unroll
        for (int rp = 0; rp < 4; rp++)
            NsP[tid * 4 + rp] = make_float2(nv[2 * rp], nv[2 * rp + 1]);
    }
    __syncthreads();

    // ================= Phase 4: pa/pb via staged W1 (100 rows x 300) ========
    if (tid < 500) {
        const float2* srcw = reinterpret_cast<const float2*>(W1w);
        float2 sv[30];
#pragma unroll
        for (int k = 0; k < 30; k++) sv[k] = srcw[k * 500 + tid];
#pragma unroll
        for (int k = 0; k < 30; k++) {
            int idx = k * 500 + tid;
            int row = idx / 150, col = idx - row * 150;
            Ws2[row * 151 + col] = sv[k];
        }
    }
    __syncthreads();

    ull acc[4] = {0, 0, 0, 0};
    if (tid < 500) {
        const float2* wr = Ws2 + oj * 151 + seg * 30;    // row oj: e=oj>>1, half=oj&1
        const int dbase = seg * 60;
        const ulonglong2* nsv = reinterpret_cast<const ulonglong2*>(NsP);
#pragma unroll 6
        for (int i = 0; i < 30; i++) {
            float2 wv = wr[i];
            int d = dbase + 2 * i;
            ulonglong2 p0 = nsv[d * 2],     p1 = nsv[d * 2 + 1];
            ulonglong2 q0 = nsv[d * 2 + 2], q1 = nsv[d * 2 + 3];
            ull wx = pk2(wv.x, wv.x);
            acc[0] = f2fma(wx, p0.x, acc[0]);
            acc[1] = f2fma(wx, p0.y, acc[1]);
            acc[2] = f2fma(wx, p1.x, acc[2]);
            acc[3] = f2fma(wx, p1.y, acc[3]);
            ull wy = pk2(wv.y, wv.y);
            acc[0] = f2fma(wy, q0.x, acc[0]);
            acc[1] = f2fma(wy, q0.y, acc[1]);
            acc[2] = f2fma(wy, q1.x, acc[2]);
            acc[3] = f2fma(wy, q1.y, acc[3]);
        }
    }
    if (tid < 500 && seg) {
        int base = ((seg - 1) * 100 + oj) * 4;
#pragma unroll
        for (int rp = 0; rp < 4; rp++) GH[base + rp] = acc[rp];
    }
    __syncthreads();
    if (tid < 100) {
        int e = tid >> 1, half = tid & 1;    // W1 row tid = [e][half*D .. ]
        float pv[RROWS];
#pragma unroll
        for (int rp = 0; rp < 4; rp++) {
            ull v = acc[rp];
#pragma unroll
            for (int s = 0; s < 4; s++) v = f2add(v, GH[(s * 100 + tid) * 4 + rp]);
            upk2(v, pv[2 * rp], pv[2 * rp + 1]);
        }
        float* dst = (half == 0 ? g_Pa : g_Pb) + (size_t)(b * SS + s0) * DEPC + e;
#pragma unroll
        for (int r = 0; r < RROWS; r++) dst[r * DEPC] = pv[r];
    }
}

// =======================================================================
// k_edge: edge[b,i,j,e] = pa[b,j,e] + pb[b,i,e] + W1_b[e]
// =======================================================================
__global__ __launch_bounds__(400) void k_edge(const float* __restrict__ W1b,
                                              float* __restrict__ edge) {
    const int bi0 = blockIdx.x * 2;
    const int b   = bi0 >> 7;
    const int tid = threadIdx.x;
    const int e2  = tid % 25;
    const int j0  = tid / 25;

    float2 w = reinterpret_cast<const float2*>(W1b)[e2];
    const ull* pa = reinterpret_cast<const ull*>(g_Pa + (size_t)b * SS * DEPC);
    ull pav[8];
#pragma unroll
    for (int k = 0; k < 8; k++) pav[k] = pa[(j0 + 16 * k) * 25 + e2];

#pragma unroll
    for (int r = 0; r < 2; r++) {
        int bi = bi0 + r;
        float2 pv = reinterpret_cast<const float2*>(g_Pb + (size_t)bi * DEPC)[e2];
        ull pr = pk2(pv.x + w.x, pv.y + w.y);
        ull* out = reinterpret_cast<ull*>(edge + (size_t)bi * SS * DEPC);
#pragma unroll
        for (int k = 0; k < 8; k++) out[(j0 + 16 * k) * 25 + e2] = f2add(pav[k], pr);
    }
}

// =======================================================================
extern "C" void kernel_launch(void* const* d_in, const int* in_sizes, int n_in,
                              void* d_out, int out_size) {
    const float* wps = (const float*)d_in[0];
    /* d_in[1] = weight_adj (int64) — unused */
    const float* x   = (const float*)d_in[2];
    const float* sl  = (const float*)d_in[3];
    const float* Ww  = (const float*)d_in[4];
    const float* Wb  = (const float*)d_in[5];
    const float* lna = (const float*)d_in[6];
    const float* lnb = (const float*)d_in[7];
    const float* W1w = (const float*)d_in[8];
    const float* W1b = (const float*)d_in[9];

    float* out  = (float*)d_out;
    float* node = out;
    float* edge = out + BB * SS * DD;

    cudaFuncSetAttribute((const void*)k_compute,
                         cudaFuncAttributeMaxDynamicSharedMemorySize, SMEM_BYTES);

    k_reduce <<<BB * SS, 256>>>(wps, sl);
    k_compute<<<BB * (SS / RROWS), NTHR, SMEM_BYTES>>>(x, Ww, Wb, lna, lnb, W1w, node);
    k_edge   <<<BB * SS / 2, 400>>>(W1b, edge);
}